// round 2
// baseline (speedup 1.0000x reference)
#include <cuda_runtime.h>

#define NN   4096
#define FIN  512
#define HH   8
#define FO   64
#define LALPHA 0.2f
#define NW   (NN/32)   // 128 mask words per row

// ---------------- scratch (device globals; no allocs allowed) ----------------
__device__ float    g_Wh[(size_t)HH*NN*FO];     // [h][n][f]  8 MB
__device__ unsigned g_bits[(size_t)NN*NW];      // bit-packed adjacency, 2 MB
__device__ float    g_s [HH*NN], g_E1[HH*NN], g_E2[HH*NN];
__device__ float    g_dd[HH*NN], g_F1[HH*NN], g_F2[HH*NN];

// ---------------- K1: bit-pack adjacency via warp ballot ----------------
__global__ void k_bitpack(const int* __restrict__ adj) {
    int t = blockIdx.x * blockDim.x + threadIdx.x;
    int w = t >> 5;               // word index 0..524287
    int lane = t & 31;
    int v = adj[(size_t)w * 32 + lane];
    unsigned b = __ballot_sync(0xffffffffu, v > 0);
    if (lane == 0) g_bits[w] = b;
}

// ---------------- K2: Wh[h] = X @ W[h]   (tiled SGEMM, 128x64 per block) ----------------
__global__ __launch_bounds__(256) void k_wh(const float* __restrict__ X,
                                            const float* __restrict__ W) {
    __shared__ float As[32][129];   // [k][i], padded -> conflict-free transpose store
    __shared__ float Bs[32][64];    // [k][f]
    const int h  = blockIdx.y;
    const int i0 = blockIdx.x * 128;
    const int tid = threadIdx.x;
    const int tx = tid & 15;        // feature group: feats tx*4..tx*4+3
    const int ty = tid >> 4;        // row group:     rows  ty*8..ty*8+7
    const float* Wb = W + (size_t)h * FIN * FO;

    float acc[8][4] = {};

    for (int kt = 0; kt < FIN; kt += 32) {
        __syncthreads();
        // A tile: transpose [i][k] -> [k][i]
        {
            int k4 = tid & 7;          // 0..7 (float4 along k)
            int il = tid >> 3;         // 0..31
            #pragma unroll
            for (int rep = 0; rep < 4; rep++) {
                int i = il + rep * 32;
                float4 f = *(const float4*)&X[(size_t)(i0 + i) * FIN + kt + k4 * 4];
                As[k4*4+0][i] = f.x; As[k4*4+1][i] = f.y;
                As[k4*4+2][i] = f.z; As[k4*4+3][i] = f.w;
            }
        }
        // B tile: direct copy
        {
            int f4 = tid & 15;
            int k  = tid >> 4;
            #pragma unroll
            for (int rep = 0; rep < 2; rep++) {
                int kk = k + rep * 16;
                *(float4*)&Bs[kk][f4*4] =
                    *(const float4*)&Wb[(size_t)(kt + kk) * FO + f4 * 4];
            }
        }
        __syncthreads();
        #pragma unroll
        for (int k = 0; k < 32; k++) {
            float a[8];
            #pragma unroll
            for (int r = 0; r < 8; r++) a[r] = As[k][ty*8 + r];
            float4 vv = *(const float4*)&Bs[k][tx*4];
            #pragma unroll
            for (int r = 0; r < 8; r++) {
                acc[r][0] += a[r] * vv.x;
                acc[r][1] += a[r] * vv.y;
                acc[r][2] += a[r] * vv.z;
                acc[r][3] += a[r] * vv.w;
            }
        }
    }
    #pragma unroll
    for (int r = 0; r < 8; r++) {
        int i = i0 + ty*8 + r;
        float4 o; o.x = acc[r][0]; o.y = acc[r][1]; o.z = acc[r][2]; o.w = acc[r][3];
        *(float4*)&g_Wh[((size_t)h * NN + i) * FO + tx * 4] = o;
    }
}

// ---------------- K3: per-(head,node) terms s,d and 4 exponentials ----------------
// One warp per (h,n): 64-wide dot products + shuffle reduce.
__global__ void k_nodes(const float* __restrict__ a_src,
                        const float* __restrict__ a_dst) {
    int gw   = blockIdx.x * (blockDim.x >> 5) + (threadIdx.x >> 5);
    int lane = threadIdx.x & 31;
    int h = gw >> 12;          // /4096
    int n = gw & (NN - 1);
    const float* wr = g_Wh + ((size_t)h * NN + n) * FO;
    float w0 = wr[lane], w1 = wr[lane + 32];
    float s = w0 * a_src[h*FO + lane] + w1 * a_src[h*FO + lane + 32];
    float d = w0 * a_dst[h*FO + lane] + w1 * a_dst[h*FO + lane + 32];
    #pragma unroll
    for (int off = 16; off; off >>= 1) {
        s += __shfl_xor_sync(0xffffffffu, s, off);
        d += __shfl_xor_sync(0xffffffffu, d, off);
    }
    if (lane == 0) {
        int idx = h * NN + n;
        g_s [idx] = s; g_E1[idx] = __expf(s); g_E2[idx] = __expf(LALPHA * s);
        g_dd[idx] = d; g_F1[idx] = __expf(d); g_F2[idx] = __expf(LALPHA * d);
    }
}

// ---------------- K4: fused masked-softmax attention + PV + ELU ----------------
// Block = (i-tile of 128 rows, head h). Loop j in tiles of 32:
//   phase 1: P[j][i] = adj_ij ? (s_i+d_j>=0 ? E1_i*F1_j : E2_i*F2_j) : 0  (+ Z accumulation)
//   phase 2: acc += P^T-tile @ Wh-tile  (8x4 register tiling, FFMA-bound)
__global__ __launch_bounds__(256) void k_attn(float* __restrict__ out) {
    __shared__ float    Ps[32][129];     // [j][i] padded (conflict-free STS & broadcast LDS)
    __shared__ float    Vs[32][64];      // Wh tile [j][f]
    __shared__ float    sS[128], sE1[128], sE2[128];
    __shared__ float    dD[32], dF1[32], dF2[32];
    __shared__ unsigned wB[128];
    __shared__ float    Zs[128];

    const int h  = blockIdx.y;
    const int i0 = blockIdx.x * 128;
    const int tid  = threadIdx.x;
    const int tx   = tid & 15;   // phase-2 feature group
    const int ty   = tid >> 4;   // phase-2 row group
    const int lane = tid & 31;   // phase-1 j within tile
    const int wrp  = tid >> 5;   // phase-1 row block (16 rows each)

    if (tid < 128) {
        int idx = h * NN + i0 + tid;
        sS[tid] = g_s[idx]; sE1[tid] = g_E1[idx]; sE2[tid] = g_E2[idx];
    }

    float acc[8][4] = {};
    float z[16] = {};
    const unsigned mybit = 1u << lane;

    for (int jt = 0; jt < NW; jt++) {
        const int j0 = jt * 32;
        __syncthreads();
        // V tile (Wh rows j0..j0+31) — served from L2 (Wh[h] = 1 MB, resident)
        {
            int f4 = tid & 15, j = tid >> 4;
            #pragma unroll
            for (int rep = 0; rep < 2; rep++) {
                int jj = j + rep * 16;
                *(float4*)&Vs[jj][f4*4] =
                    *(const float4*)&g_Wh[((size_t)h * NN + j0 + jj) * FO + f4 * 4];
            }
        }
        if (tid < 32) {
            int idx = h * NN + j0 + tid;
            dD[tid] = g_dd[idx]; dF1[tid] = g_F1[idx]; dF2[tid] = g_F2[idx];
        }
        if (tid < 128) wB[tid] = g_bits[(size_t)(i0 + tid) * NW + jt];
        __syncthreads();

        // ---- phase 1: logits -> unnormalized softmax weights (no exp here!) ----
        {
            float dj = dD[lane], f1 = dF1[lane], f2 = dF2[lane];
            #pragma unroll
            for (int r = 0; r < 16; r++) {
                int i = wrp * 16 + r;
                float t = sS[i] + dj;
                float w = (t >= 0.f) ? sE1[i] * f1 : sE2[i] * f2;
                w = (wB[i] & mybit) ? w : 0.f;
                Ps[lane][i] = w;
                z[r] += w;
            }
        }
        __syncthreads();

        // ---- phase 2: acc[TI x 64] += P[TI x 32] @ V[32 x 64] ----
        #pragma unroll
        for (int k = 0; k < 32; k++) {
            float a[8];
            #pragma unroll
            for (int r = 0; r < 8; r++) a[r] = Ps[k][ty*8 + r];
            float4 vv = *(const float4*)&Vs[k][tx*4];
            #pragma unroll
            for (int r = 0; r < 8; r++) {
                acc[r][0] += a[r] * vv.x;
                acc[r][1] += a[r] * vv.y;
                acc[r][2] += a[r] * vv.z;
                acc[r][3] += a[r] * vv.w;
            }
        }
    }

    // ---- row-sum (softmax denominator) cross-lane reduction ----
    #pragma unroll
    for (int r = 0; r < 16; r++) {
        float v = z[r];
        #pragma unroll
        for (int off = 16; off; off >>= 1) v += __shfl_xor_sync(0xffffffffu, v, off);
        z[r] = v;
    }
    __syncthreads();
    if (lane == 0) {
        #pragma unroll
        for (int r = 0; r < 16; r++) Zs[wrp*16 + r] = z[r];
    }
    __syncthreads();

    // ---- normalize + ELU + write [N, H*FO] ----
    #pragma unroll
    for (int r = 0; r < 8; r++) {
        int il = ty*8 + r;
        float zi = 1.f / Zs[il];
        float4 o;
        o.x = acc[r][0] * zi; o.y = acc[r][1] * zi;
        o.z = acc[r][2] * zi; o.w = acc[r][3] * zi;
        o.x = (o.x > 0.f) ? o.x : expm1f(o.x);
        o.y = (o.y > 0.f) ? o.y : expm1f(o.y);
        o.z = (o.z > 0.f) ? o.z : expm1f(o.z);
        o.w = (o.w > 0.f) ? o.w : expm1f(o.w);
        *(float4*)&out[(size_t)(i0 + il) * (HH * FO) + h * FO + tx * 4] = o;
    }
}

// ---------------- launcher ----------------
extern "C" void kernel_launch(void* const* d_in, const int* in_sizes, int n_in,
                              void* d_out, int out_size) {
    const float* X     = (const float*)d_in[0];
    const int*   adj   = (const int*)  d_in[1];
    const float* W     = (const float*)d_in[2];
    const float* a_src = (const float*)d_in[3];
    const float* a_dst = (const float*)d_in[4];
    float* out = (float*)d_out;

    k_bitpack<<<(NN * NW) / 8, 256>>>(adj);                // 65536 blocks, warp ballot
    k_wh     <<<dim3(NN/128, HH), 256>>>(X, W);            // 256 blocks
    k_nodes  <<<(HH * NN) / 8, 256>>>(a_src, a_dst);       // 4096 blocks (8 warps each)
    k_attn   <<<dim3(NN/128, HH), 256>>>(out);             // 256 blocks, the big one
}

// round 3
// speedup vs baseline: 1.2420x; 1.2420x over previous
#include <cuda_runtime.h>

#define NN   4096
#define FIN  512
#define HH   8
#define FO   64
#define LALPHA 0.2f
#define NW   (NN/32)   // 128 mask words per row

typedef unsigned long long u64;

// ---------------- f32x2 packed helpers (sm_100+ packed fp32 pipe) ----------------
__device__ __forceinline__ u64 pk2(float lo, float hi) {
    u64 r; asm("mov.b64 %0, {%1,%2};" : "=l"(r) : "f"(lo), "f"(hi)); return r;
}
__device__ __forceinline__ void fma2(u64 &d, u64 a, u64 b) {
    asm("fma.rn.f32x2 %0, %1, %2, %3;" : "=l"(d) : "l"(a), "l"(b), "l"(d));
}
__device__ __forceinline__ void add2(u64 &d, u64 a) {
    asm("add.rn.f32x2 %0, %1, %2;" : "=l"(d) : "l"(d), "l"(a));
}
__device__ __forceinline__ void upk2(float &lo, float &hi, u64 v) {
    asm("mov.b64 {%0,%1}, %2;" : "=f"(lo), "=f"(hi) : "l"(v));
}

// ---------------- scratch (device globals; no allocs allowed) ----------------
__device__ float    g_Wh[(size_t)HH*NN*FO];     // [h][n][f]  8 MB
__device__ unsigned g_bits[(size_t)NN*NW];      // bit-packed adjacency, 2 MB
__device__ float    g_s [HH*NN], g_E1[HH*NN], g_E2[HH*NN];
__device__ float    g_dd[HH*NN], g_F1[HH*NN], g_F2[HH*NN];

// ---------------- K1: bit-pack adjacency via warp ballot ----------------
__global__ void k_bitpack(const int* __restrict__ adj) {
    int t = blockIdx.x * blockDim.x + threadIdx.x;
    int w = t >> 5;
    int lane = t & 31;
    int v = adj[(size_t)w * 32 + lane];
    unsigned b = __ballot_sync(0xffffffffu, v > 0);
    if (lane == 0) g_bits[w] = b;
}

// ---------------- K2: Wh[h] = X @ W[h]   (tiled SGEMM, f32x2 inner) ----------------
__global__ __launch_bounds__(256) void k_wh(const float* __restrict__ X,
                                            const float* __restrict__ W) {
    __shared__ float As[32][130];   // [k][i], pad 130: 8B-aligned rows for LDS.64
    __shared__ float Bs[32][64];    // [k][f]
    const int h  = blockIdx.y;
    const int i0 = blockIdx.x * 128;
    const int tid = threadIdx.x;
    const int tx = tid & 15;        // feature group: feats tx*4..tx*4+3
    const int ty = tid >> 4;        // row group:     rows  ty*8..ty*8+7 (4 pairs)
    const float* Wb = W + (size_t)h * FIN * FO;

    u64 acc[4][4] = {};             // [i-pair][f] packed over i

    for (int kt = 0; kt < FIN; kt += 32) {
        __syncthreads();
        // A tile: transpose [i][k] -> [k][i]
        {
            int k4 = tid & 7;
            int il = tid >> 3;
            #pragma unroll
            for (int rep = 0; rep < 4; rep++) {
                int i = il + rep * 32;
                float4 f = *(const float4*)&X[(size_t)(i0 + i) * FIN + kt + k4 * 4];
                As[k4*4+0][i] = f.x; As[k4*4+1][i] = f.y;
                As[k4*4+2][i] = f.z; As[k4*4+3][i] = f.w;
            }
        }
        // B tile
        {
            int f4 = tid & 15;
            int k  = tid >> 4;
            #pragma unroll
            for (int rep = 0; rep < 2; rep++) {
                int kk = k + rep * 16;
                *(float4*)&Bs[kk][f4*4] =
                    *(const float4*)&Wb[(size_t)(kt + kk) * FO + f4 * 4];
            }
        }
        __syncthreads();
        #pragma unroll
        for (int k = 0; k < 32; k++) {
            u64 p[4];
            #pragma unroll
            for (int ip = 0; ip < 4; ip++)
                p[ip] = *(const u64*)&As[k][ty*8 + 2*ip];
            float4 vv = *(const float4*)&Bs[k][tx*4];
            u64 v0 = pk2(vv.x, vv.x), v1 = pk2(vv.y, vv.y);
            u64 v2 = pk2(vv.z, vv.z), v3 = pk2(vv.w, vv.w);
            #pragma unroll
            for (int ip = 0; ip < 4; ip++) {
                fma2(acc[ip][0], p[ip], v0);
                fma2(acc[ip][1], p[ip], v1);
                fma2(acc[ip][2], p[ip], v2);
                fma2(acc[ip][3], p[ip], v3);
            }
        }
    }
    #pragma unroll
    for (int ip = 0; ip < 4; ip++) {
        float lo[4], hi[4];
        #pragma unroll
        for (int f = 0; f < 4; f++) upk2(lo[f], hi[f], acc[ip][f]);
        int i = i0 + ty*8 + 2*ip;
        float4 o0; o0.x = lo[0]; o0.y = lo[1]; o0.z = lo[2]; o0.w = lo[3];
        float4 o1; o1.x = hi[0]; o1.y = hi[1]; o1.z = hi[2]; o1.w = hi[3];
        *(float4*)&g_Wh[((size_t)h * NN + i    ) * FO + tx * 4] = o0;
        *(float4*)&g_Wh[((size_t)h * NN + i + 1) * FO + tx * 4] = o1;
    }
}

// ---------------- K3: per-(head,node) terms s,d and 4 exponentials ----------------
__global__ void k_nodes(const float* __restrict__ a_src,
                        const float* __restrict__ a_dst) {
    int gw   = blockIdx.x * (blockDim.x >> 5) + (threadIdx.x >> 5);
    int lane = threadIdx.x & 31;
    int h = gw >> 12;
    int n = gw & (NN - 1);
    const float* wr = g_Wh + ((size_t)h * NN + n) * FO;
    float w0 = wr[lane], w1 = wr[lane + 32];
    float s = w0 * a_src[h*FO + lane] + w1 * a_src[h*FO + lane + 32];
    float d = w0 * a_dst[h*FO + lane] + w1 * a_dst[h*FO + lane + 32];
    #pragma unroll
    for (int off = 16; off; off >>= 1) {
        s += __shfl_xor_sync(0xffffffffu, s, off);
        d += __shfl_xor_sync(0xffffffffu, d, off);
    }
    if (lane == 0) {
        int idx = h * NN + n;
        g_s [idx] = s; g_E1[idx] = __expf(s); g_E2[idx] = __expf(LALPHA * s);
        g_dd[idx] = d; g_F1[idx] = __expf(d); g_F2[idx] = __expf(LALPHA * d);
    }
}

// ---------------- K4: fused masked-softmax attention + PV + ELU (f32x2) ----------------
__global__ __launch_bounds__(256) void k_attn(float* __restrict__ out) {
    __shared__ float    Ps[32][130];     // [j][i], pad 130 -> 8B-aligned rows
    __shared__ float    Vs[32][64];      // Wh tile [j][f]
    __shared__ float    sS[128], sE1[128], sE2[128];
    __shared__ float    dD[32], dF1[32], dF2[32];
    __shared__ unsigned wB[128];
    __shared__ float    Zs[128];

    const int h  = blockIdx.y;
    const int i0 = blockIdx.x * 128;
    const int tid  = threadIdx.x;
    const int tx   = tid & 15;   // phase-2 feature group
    const int ty   = tid >> 4;   // phase-2 row group (8 rows = 4 pairs)
    const int lane = tid & 31;   // phase-1 j within tile
    const int wrp  = tid >> 5;   // phase-1 row block (16 rows = 8 pairs)

    if (tid < 128) {
        int idx = h * NN + i0 + tid;
        sS[tid] = g_s[idx]; sE1[tid] = g_E1[idx]; sE2[tid] = g_E2[idx];
    }

    u64 acc[4][4] = {};          // [i-pair][f] packed over i
    u64 zp[8] = {};              // packed row-sum pairs
    const unsigned mybit = 1u << lane;

    for (int jt = 0; jt < NW; jt++) {
        const int j0 = jt * 32;
        __syncthreads();
        // V tile (Wh rows j0..j0+31), L2-resident
        {
            int f4 = tid & 15, j = tid >> 4;
            #pragma unroll
            for (int rep = 0; rep < 2; rep++) {
                int jj = j + rep * 16;
                *(float4*)&Vs[jj][f4*4] =
                    *(const float4*)&g_Wh[((size_t)h * NN + j0 + jj) * FO + f4 * 4];
            }
        }
        if (tid < 32) {
            int idx = h * NN + j0 + tid;
            dD[tid] = g_dd[idx]; dF1[tid] = g_F1[idx]; dF2[tid] = g_F2[idx];
        }
        if (tid < 128) wB[tid] = g_bits[(size_t)(i0 + tid) * NW + jt];
        __syncthreads();

        // ---- phase 1: unnormalized softmax weights, no exp in the N^2 loop ----
        {
            float dj = dD[lane], f1 = dF1[lane], f2 = dF2[lane];
            #pragma unroll
            for (int q = 0; q < 8; q++) {
                int i = wrp * 16 + 2*q;
                float t0 = sS[i]   + dj;
                float w0 = (t0 >= 0.f) ? sE1[i]   * f1 : sE2[i]   * f2;
                w0 = (wB[i]   & mybit) ? w0 : 0.f;
                float t1 = sS[i+1] + dj;
                float w1 = (t1 >= 0.f) ? sE1[i+1] * f1 : sE2[i+1] * f2;
                w1 = (wB[i+1] & mybit) ? w1 : 0.f;
                u64 wp = pk2(w0, w1);
                *(u64*)&Ps[lane][i] = wp;
                add2(zp[q], wp);
            }
        }
        __syncthreads();

        // ---- phase 2: acc[128 x 64] += P[128 x 32] @ V[32 x 64], packed over i ----
        #pragma unroll
        for (int k = 0; k < 32; k++) {
            u64 p[4];
            #pragma unroll
            for (int ip = 0; ip < 4; ip++)
                p[ip] = *(const u64*)&Ps[k][ty*8 + 2*ip];
            float4 vv = *(const float4*)&Vs[k][tx*4];
            u64 v0 = pk2(vv.x, vv.x), v1 = pk2(vv.y, vv.y);
            u64 v2 = pk2(vv.z, vv.z), v3 = pk2(vv.w, vv.w);
            #pragma unroll
            for (int ip = 0; ip < 4; ip++) {
                fma2(acc[ip][0], p[ip], v0);
                fma2(acc[ip][1], p[ip], v1);
                fma2(acc[ip][2], p[ip], v2);
                fma2(acc[ip][3], p[ip], v3);
            }
        }
    }

    // ---- packed row-sum cross-lane reduction ----
    #pragma unroll
    for (int q = 0; q < 8; q++) {
        u64 v = zp[q];
        #pragma unroll
        for (int off = 16; off; off >>= 1)
            add2(v, __shfl_xor_sync(0xffffffffu, v, off));
        zp[q] = v;
    }
    __syncthreads();
    if (lane == 0) {
        #pragma unroll
        for (int q = 0; q < 8; q++) {
            float a, b; upk2(a, b, zp[q]);
            Zs[wrp*16 + 2*q] = a; Zs[wrp*16 + 2*q + 1] = b;
        }
    }
    __syncthreads();

    // ---- normalize + ELU + write [N, H*FO] ----
    #pragma unroll
    for (int ip = 0; ip < 4; ip++) {
        int il = ty*8 + 2*ip;
        float zi0 = 1.f / Zs[il], zi1 = 1.f / Zs[il + 1];
        float lo[4], hi[4];
        #pragma unroll
        for (int f = 0; f < 4; f++) upk2(lo[f], hi[f], acc[ip][f]);
        float4 o0, o1;
        o0.x = lo[0]*zi0; o0.y = lo[1]*zi0; o0.z = lo[2]*zi0; o0.w = lo[3]*zi0;
        o1.x = hi[0]*zi1; o1.y = hi[1]*zi1; o1.z = hi[2]*zi1; o1.w = hi[3]*zi1;
        o0.x = (o0.x > 0.f) ? o0.x : expm1f(o0.x);
        o0.y = (o0.y > 0.f) ? o0.y : expm1f(o0.y);
        o0.z = (o0.z > 0.f) ? o0.z : expm1f(o0.z);
        o0.w = (o0.w > 0.f) ? o0.w : expm1f(o0.w);
        o1.x = (o1.x > 0.f) ? o1.x : expm1f(o1.x);
        o1.y = (o1.y > 0.f) ? o1.y : expm1f(o1.y);
        o1.z = (o1.z > 0.f) ? o1.z : expm1f(o1.z);
        o1.w = (o1.w > 0.f) ? o1.w : expm1f(o1.w);
        *(float4*)&out[(size_t)(i0 + il    ) * (HH * FO) + h * FO + tx * 4] = o0;
        *(float4*)&out[(size_t)(i0 + il + 1) * (HH * FO) + h * FO + tx * 4] = o1;
    }
}

// ---------------- launcher ----------------
extern "C" void kernel_launch(void* const* d_in, const int* in_sizes, int n_in,
                              void* d_out, int out_size) {
    const float* X     = (const float*)d_in[0];
    const int*   adj   = (const int*)  d_in[1];
    const float* W     = (const float*)d_in[2];
    const float* a_src = (const float*)d_in[3];
    const float* a_dst = (const float*)d_in[4];
    float* out = (float*)d_out;

    k_bitpack<<<(NN * NW) / 8, 256>>>(adj);
    k_wh     <<<dim3(NN/128, HH), 256>>>(X, W);
    k_nodes  <<<(HH * NN) / 8, 256>>>(a_src, a_dst);
    k_attn   <<<dim3(NN/128, HH), 256>>>(out);
}

// round 5
// speedup vs baseline: 1.3220x; 1.0644x over previous
#include <cuda_runtime.h>
#include <cstdint>

#define NN   4096
#define FIN  512
#define HH   8
#define FO   64
#define LALPHA 0.2f
#define NW   (NN/32)   // 128 mask words per row
#define JT   32
#define NT   (NN/JT)   // 128 j-tiles
#define PAD  132       // row pad: 132 floats = 528 B, 16B-aligned rows

typedef unsigned long long u64;

// ---------------- f32x2 packed helpers ----------------
__device__ __forceinline__ u64 pk2(float lo, float hi) {
    u64 r; asm("mov.b64 %0, {%1,%2};" : "=l"(r) : "f"(lo), "f"(hi)); return r;
}
__device__ __forceinline__ void fma2(u64 &d, u64 a, u64 b) {
    asm("fma.rn.f32x2 %0, %1, %2, %3;" : "=l"(d) : "l"(a), "l"(b), "l"(d));
}
__device__ __forceinline__ void add2(u64 &d, u64 a) {
    asm("add.rn.f32x2 %0, %1, %2;" : "=l"(d) : "l"(d), "l"(a));
}
__device__ __forceinline__ void upk2(float &lo, float &hi, u64 v) {
    asm("mov.b64 {%0,%1}, %2;" : "=f"(lo), "=f"(hi) : "l"(v));
}

// ---------------- scratch (device globals) ----------------
__device__ float    g_Wh[(size_t)HH*NN*FO];     // [h][n][f]  8 MB
__device__ unsigned g_bits[(size_t)NN*NW];      // bit-packed adjacency, 2 MB
__device__ float    g_s [HH*NN], g_E1[HH*NN], g_E2[HH*NN];
__device__ float    g_dd[HH*NN], g_F1[HH*NN], g_F2[HH*NN];

// ---------------- K1: bit-pack adjacency ----------------
__global__ void k_bitpack(const int* __restrict__ adj) {
    int t = blockIdx.x * blockDim.x + threadIdx.x;
    int w = t >> 5, lane = t & 31;
    int v = adj[(size_t)w * 32 + lane];
    unsigned b = __ballot_sync(0xffffffffu, v > 0);
    if (lane == 0) g_bits[w] = b;
}

// ---------------- K2: Wh[h] = X @ W[h] (f32x2, LDS.128) ----------------
__global__ __launch_bounds__(256, 2) void k_wh(const float* __restrict__ X,
                                               const float* __restrict__ W) {
    __shared__ float As[32][PAD];
    __shared__ float Bs[32][64];
    const int h = blockIdx.y, i0 = blockIdx.x * 128, tid = threadIdx.x;
    const int tx = tid & 15, ty = tid >> 4;
    const float* Wb = W + (size_t)h * FIN * FO;
    u64 acc[4][4] = {};
    for (int kt = 0; kt < FIN; kt += 32) {
        __syncthreads();
        {
            int k4 = tid & 7, il = tid >> 3;
            #pragma unroll
            for (int rep = 0; rep < 4; rep++) {
                int i = il + rep * 32;
                float4 f = *(const float4*)&X[(size_t)(i0 + i) * FIN + kt + k4 * 4];
                As[k4*4+0][i] = f.x; As[k4*4+1][i] = f.y;
                As[k4*4+2][i] = f.z; As[k4*4+3][i] = f.w;
            }
        }
        {
            int f4 = tid & 15, k = tid >> 4;
            #pragma unroll
            for (int rep = 0; rep < 2; rep++) {
                int kk = k + rep * 16;
                *(float4*)&Bs[kk][f4*4] = *(const float4*)&Wb[(size_t)(kt+kk)*FO + f4*4];
            }
        }
        __syncthreads();
        #pragma unroll
        for (int k = 0; k < 32; k++) {
            float4 pa = *(const float4*)&As[k][ty*8];
            float4 pb = *(const float4*)&As[k][ty*8 + 4];
            u64 p[4] = { pk2(pa.x, pa.y), pk2(pa.z, pa.w),
                         pk2(pb.x, pb.y), pk2(pb.z, pb.w) };
            float4 vv = *(const float4*)&Bs[k][tx*4];
            u64 v0 = pk2(vv.x, vv.x), v1 = pk2(vv.y, vv.y);
            u64 v2 = pk2(vv.z, vv.z), v3 = pk2(vv.w, vv.w);
            #pragma unroll
            for (int ip = 0; ip < 4; ip++) {
                fma2(acc[ip][0], p[ip], v0); fma2(acc[ip][1], p[ip], v1);
                fma2(acc[ip][2], p[ip], v2); fma2(acc[ip][3], p[ip], v3);
            }
        }
    }
    #pragma unroll
    for (int ip = 0; ip < 4; ip++) {
        float lo[4], hi[4];
        #pragma unroll
        for (int f = 0; f < 4; f++) upk2(lo[f], hi[f], acc[ip][f]);
        int i = i0 + ty*8 + 2*ip;
        float4 o0 = {lo[0], lo[1], lo[2], lo[3]};
        float4 o1 = {hi[0], hi[1], hi[2], hi[3]};
        *(float4*)&g_Wh[((size_t)h*NN + i    )*FO + tx*4] = o0;
        *(float4*)&g_Wh[((size_t)h*NN + i + 1)*FO + tx*4] = o1;
    }
}

// ---------------- K3: per-(h,n) s,d + exp factors ----------------
__global__ void k_nodes(const float* __restrict__ a_src,
                        const float* __restrict__ a_dst) {
    int gw = blockIdx.x * (blockDim.x >> 5) + (threadIdx.x >> 5);
    int lane = threadIdx.x & 31;
    int h = gw >> 12, n = gw & (NN - 1);
    const float* wr = g_Wh + ((size_t)h * NN + n) * FO;
    float w0 = wr[lane], w1 = wr[lane + 32];
    float s = w0 * a_src[h*FO + lane] + w1 * a_src[h*FO + lane + 32];
    float d = w0 * a_dst[h*FO + lane] + w1 * a_dst[h*FO + lane + 32];
    #pragma unroll
    for (int off = 16; off; off >>= 1) {
        s += __shfl_xor_sync(0xffffffffu, s, off);
        d += __shfl_xor_sync(0xffffffffu, d, off);
    }
    if (lane == 0) {
        int idx = h * NN + n;
        g_s [idx] = s; g_E1[idx] = __expf(s); g_E2[idx] = __expf(LALPHA * s);
        g_dd[idx] = d; g_F1[idx] = __expf(d); g_F2[idx] = __expf(LALPHA * d);
    }
}

// ---------------- K4: fused attention, double-buffered, f32x2 ----------------
struct SmemAttn {
    float    Ps[2][JT][PAD];   // [buf][j][i]  33792 B
    float    Vs[2][JT][FO];    //              16384 B
    float    dD[2][JT], dF1[2][JT], dF2[2][JT];
    unsigned wB[2][128];
    float    sS[128];
    float    Zs[128];
};
#define SMEM_ATTN sizeof(SmemAttn)

__global__ __launch_bounds__(256, 2) void k_attn(float* __restrict__ out) {
    extern __shared__ char smraw[];
    SmemAttn* sm = (SmemAttn*)smraw;
    const int h  = blockIdx.y;
    const int i0 = blockIdx.x * 128;
    const int tid  = threadIdx.x;
    const int tx   = tid & 15;    // phase-2 feature group
    const int ty   = tid >> 4;    // phase-2 row group (8 rows)
    const int lane = tid & 31;    // phase-1 j within tile
    const int wrp  = tid >> 5;    // phase-1 row block (16 rows)

    if (tid < 128) sm->sS[tid] = g_s[h*NN + i0 + tid];

    // phase-1 E factors held in registers (fixed i-range per thread, loaded once)
    float e1r[16], e2r[16];
    #pragma unroll
    for (int q = 0; q < 16; q++) {
        int idx = h*NN + i0 + wrp*16 + q;
        e1r[q] = g_E1[idx]; e2r[q] = g_E2[idx];
    }

    u64 acc[4][4] = {};
    u64 zp[8] = {};
    const unsigned mybit = 1u << lane;

    // tile loader: V (Wh rows), d-terms, mask words  -> buffer b
    auto load_tile = [&](int jt, int b) {
        const int j0 = jt * JT;
        int f4 = tid & 15, j = tid >> 4;
        #pragma unroll
        for (int rep = 0; rep < 2; rep++) {
            int jj = j + rep * 16;
            *(float4*)&sm->Vs[b][jj][f4*4] =
                *(const float4*)&g_Wh[((size_t)h*NN + j0 + jj)*FO + f4*4];
        }
        if (tid < 32) {
            int idx = h*NN + j0 + tid;
            sm->dD[b][tid] = g_dd[idx]; sm->dF1[b][tid] = g_F1[idx]; sm->dF2[b][tid] = g_F2[idx];
        }
        if (tid < 128) sm->wB[b][tid] = g_bits[(size_t)(i0 + tid) * NW + jt];
    };

    load_tile(0, 0);
    __syncthreads();

    for (int jt = 0; jt < NT; jt++) {
        const int b = jt & 1;

        // ---- phase 1: P weights (quads, STS.128), Z accumulation ----
        {
            float dj = sm->dD[b][lane], f1 = sm->dF1[b][lane], f2 = sm->dF2[b][lane];
            #pragma unroll
            for (int q = 0; q < 4; q++) {
                float4 wv;
                float* wp = &wv.x;
                #pragma unroll
                for (int r = 0; r < 4; r++) {
                    int ii = q*4 + r;
                    int i  = wrp*16 + ii;
                    float t = sm->sS[i] + dj;
                    float v = (t >= 0.f) ? e1r[ii]*f1 : e2r[ii]*f2;
                    wp[r] = (sm->wB[b][i] & mybit) ? v : 0.f;
                }
                *(float4*)&sm->Ps[b][lane][wrp*16 + q*4] = wv;
                add2(zp[2*q],   pk2(wv.x, wv.y));
                add2(zp[2*q+1], pk2(wv.z, wv.w));
            }
        }
        // prefetch next tile into the other buffer (completes under phase 2)
        if (jt + 1 < NT) load_tile(jt + 1, b ^ 1);
        __syncthreads();

        // ---- phase 2: acc += P^T @ V   (LDS.128 quads, FFMA2) ----
        #pragma unroll
        for (int k = 0; k < 32; k++) {
            float4 pa = *(const float4*)&sm->Ps[b][k][ty*8];
            float4 pb = *(const float4*)&sm->Ps[b][k][ty*8 + 4];
            u64 p[4] = { pk2(pa.x, pa.y), pk2(pa.z, pa.w),
                         pk2(pb.x, pb.y), pk2(pb.z, pb.w) };
            float4 vv = *(const float4*)&sm->Vs[b][k][tx*4];
            u64 v0 = pk2(vv.x, vv.x), v1 = pk2(vv.y, vv.y);
            u64 v2 = pk2(vv.z, vv.z), v3 = pk2(vv.w, vv.w);
            #pragma unroll
            for (int ip = 0; ip < 4; ip++) {
                fma2(acc[ip][0], p[ip], v0); fma2(acc[ip][1], p[ip], v1);
                fma2(acc[ip][2], p[ip], v2); fma2(acc[ip][3], p[ip], v3);
            }
        }
        __syncthreads();   // buffer b free for overwrite at jt+2
    }

    // ---- packed row-sum cross-lane reduction ----
    #pragma unroll
    for (int q = 0; q < 8; q++) {
        u64 v = zp[q];
        #pragma unroll
        for (int off = 16; off; off >>= 1)
            add2(v, __shfl_xor_sync(0xffffffffu, v, off));
        zp[q] = v;
    }
    if (lane == 0) {
        #pragma unroll
        for (int q = 0; q < 8; q++) {
            float a, b2; upk2(a, b2, zp[q]);
            sm->Zs[wrp*16 + 2*q] = a; sm->Zs[wrp*16 + 2*q + 1] = b2;
        }
    }
    __syncthreads();

    // ---- normalize + ELU + store [N, H*FO] ----
    #pragma unroll
    for (int ip = 0; ip < 4; ip++) {
        int il = ty*8 + 2*ip;
        float zi0 = 1.f / sm->Zs[il], zi1 = 1.f / sm->Zs[il + 1];
        float lo[4], hi[4];
        #pragma unroll
        for (int f = 0; f < 4; f++) upk2(lo[f], hi[f], acc[ip][f]);
        float4 o0, o1;
        o0.x = lo[0]*zi0; o0.y = lo[1]*zi0; o0.z = lo[2]*zi0; o0.w = lo[3]*zi0;
        o1.x = hi[0]*zi1; o1.y = hi[1]*zi1; o1.z = hi[2]*zi1; o1.w = hi[3]*zi1;
        o0.x = (o0.x > 0.f) ? o0.x : expm1f(o0.x);
        o0.y = (o0.y > 0.f) ? o0.y : expm1f(o0.y);
        o0.z = (o0.z > 0.f) ? o0.z : expm1f(o0.z);
        o0.w = (o0.w > 0.f) ? o0.w : expm1f(o0.w);
        o1.x = (o1.x > 0.f) ? o1.x : expm1f(o1.x);
        o1.y = (o1.y > 0.f) ? o1.y : expm1f(o1.y);
        o1.z = (o1.z > 0.f) ? o1.z : expm1f(o1.z);
        o1.w = (o1.w > 0.f) ? o1.w : expm1f(o1.w);
        *(float4*)&out[(size_t)(i0 + il    ) * (HH*FO) + h*FO + tx*4] = o0;
        *(float4*)&out[(size_t)(i0 + il + 1) * (HH*FO) + h*FO + tx*4] = o1;
    }
}

// ---------------- launcher ----------------
extern "C" void kernel_launch(void* const* d_in, const int* in_sizes, int n_in,
                              void* d_out, int out_size) {
    const float* X     = (const float*)d_in[0];
    const int*   adj   = (const int*)  d_in[1];
    const float* W     = (const float*)d_in[2];
    const float* a_src = (const float*)d_in[3];
    const float* a_dst = (const float*)d_in[4];
    float* out = (float*)d_out;

    cudaFuncSetAttribute(k_attn, cudaFuncAttributeMaxDynamicSharedMemorySize, SMEM_ATTN);

    k_bitpack<<<(NN * NW) / 8, 256>>>(adj);
    k_wh     <<<dim3(NN/128, HH), 256>>>(X, W);
    k_nodes  <<<(HH * NN) / 8, 256>>>(a_src, a_dst);
    k_attn   <<<dim3(NN/128, HH), 256, SMEM_ATTN>>>(out);
}